// round 15
// baseline (speedup 1.0000x reference)
#include <cuda_runtime.h>
#include <cuda_bf16.h>
#include <cstdint>

#define HID 128
#define N_MAX 400000
__device__ float g_M[(size_t)N_MAX * HID];

// Weights pre-arranged in mma.m16n8k16 B-fragment order:
// record idx = (kt*16 + nt)*32 + lane, 16 bytes = {bh0, bh1, bl0, bl1}
// where b0 covers k = kt*16+(lane%4)*2 (+1), b1 covers k+8, n = nt*8 + lane/4.
__device__ __align__(16) unsigned char g_Bfe[5  * 16 * 32 * 16];  // edge W_i  (K=80)
__device__ __align__(16) unsigned char g_Bfn[12 * 16 * 32 * 16];  // node W_o  (K=192)

// ---------------------------------------------------------------------------
// helpers
// ---------------------------------------------------------------------------
__device__ __forceinline__ uint32_t smem_u32(const void* p) {
    uint32_t a;
    asm("{ .reg .u64 t; cvta.to.shared.u64 t, %1; cvt.u32.u64 %0, t; }" : "=r"(a) : "l"(p));
    return a;
}
__device__ __forceinline__ void ldm4(uint32_t* r, uint32_t addr) {
    asm volatile("ldmatrix.sync.aligned.m8n8.x4.shared.b16 {%0,%1,%2,%3}, [%4];"
                 : "=r"(r[0]), "=r"(r[1]), "=r"(r[2]), "=r"(r[3]) : "r"(addr));
}
__device__ __forceinline__ void mma16816(float* c, const uint32_t* a, uint32_t b0, uint32_t b1) {
    asm volatile("mma.sync.aligned.m16n8k16.row.col.f32.bf16.bf16.f32 "
                 "{%0,%1,%2,%3}, {%4,%5,%6,%7}, {%8,%9}, {%0,%1,%2,%3};"
                 : "+f"(c[0]), "+f"(c[1]), "+f"(c[2]), "+f"(c[3])
                 : "r"(a[0]), "r"(a[1]), "r"(a[2]), "r"(a[3]), "r"(b0), "r"(b1));
}
__device__ __forceinline__ void red_add_v4(float* p, float a, float b, float c, float d) {
    asm volatile("red.global.add.v4.f32 [%0], {%1,%2,%3,%4};"
                 :: "l"(p), "f"(a), "f"(b), "f"(c), "f"(d) : "memory");
}
// bf16 split of a float pair -> packed hi/lo bf16x2, memory order [va, vb] (va low)
__device__ __forceinline__ void split2(float va, float vb, uint32_t& hi, uint32_t& lo) {
    uint32_t h;
    asm("cvt.rn.bf16x2.f32 %0, %1, %2;" : "=r"(h) : "f"(vb), "f"(va));
    float ha = __uint_as_float(h << 16);
    float hb = __uint_as_float(h & 0xFFFF0000u);
    float la = va - ha, lb = vb - hb;
    uint32_t l;
    asm("cvt.rn.bf16x2.f32 %0, %1, %2;" : "=r"(l) : "f"(lb), "f"(la));
    hi = h; lo = l;
}
// stage n4 float4s (4 k each) as split bf16 pairs at byte offset `off` (8B per float4)
template<int N4>
__device__ __forceinline__ void stage4(char* aH, char* aL, uint32_t off, const float4* g) {
    #pragma unroll
    for (int j = 0; j < N4; j++) {
        float4 v = g[j];
        uint32_t h, lo;
        split2(v.x, v.y, h, lo);
        *(uint32_t*)(aH + off + j * 8) = h;  *(uint32_t*)(aL + off + j * 8) = lo;
        split2(v.z, v.w, h, lo);
        *(uint32_t*)(aH + off + j * 8 + 4) = h;  *(uint32_t*)(aL + off + j * 8 + 4) = lo;
    }
}

#define RSTRE 176   // edge A row stride: 80 k * 2B + 16B pad (8-phase ldmatrix)
#define RSTRN 208   // node A row stride per phase: 96 k * 2B + 16B pad (13*16, odd -> 8-phase)

// ---------------------------------------------------------------------------
// Kernel P: write weights in B-fragment order (hi/lo split)
// ---------------------------------------------------------------------------
__global__ void k_prep(const float* __restrict__ Wi, const float* __restrict__ Wo) {
    int t = blockIdx.x * blockDim.x + threadIdx.x;
    if (t < 5 * 16 * 32) {
        int l = t & 31, nt = (t >> 5) & 15, kt = t >> 9;
        int n = nt * 8 + (l >> 2), k0 = kt * 16 + (l & 3) * 2;
        float v00 = Wi[k0 * 128 + n],       v01 = Wi[(k0 + 1) * 128 + n];
        float v10 = Wi[(k0 + 8) * 128 + n], v11 = Wi[(k0 + 9) * 128 + n];
        uint32_t h0, l0, h1, l1;
        split2(v00, v01, h0, l0);
        split2(v10, v11, h1, l1);
        ((uint4*)g_Bfe)[t] = make_uint4(h0, h1, l0, l1);
    }
    int t2 = t - 5 * 16 * 32;
    if (t2 >= 0 && t2 < 12 * 16 * 32) {
        int l = t2 & 31, nt = (t2 >> 5) & 15, kt = t2 >> 9;
        int n = nt * 8 + (l >> 2), k0 = kt * 16 + (l & 3) * 2;
        float v00 = Wo[k0 * 128 + n],       v01 = Wo[(k0 + 1) * 128 + n];
        float v10 = Wo[(k0 + 8) * 128 + n], v11 = Wo[(k0 + 9) * 128 + n];
        uint32_t h0, l0, h1, l1;
        split2(v00, v01, h0, l0);
        split2(v10, v11, h1, l1);
        ((uint4*)g_Bfn)[t2] = make_uint4(h0, h1, l0, l1);
    }
}

// ---------------------------------------------------------------------------
// Kernel 0: zero the message buffer
// ---------------------------------------------------------------------------
__global__ void k_zero(int n4) {
    int i = blockIdx.x * blockDim.x + threadIdx.x;
    if (i < n4) ((float4*)g_M)[i] = make_float4(0.f, 0.f, 0.f, 0.f);
}

// ---------------------------------------------------------------------------
// Kernel 1: edges. h0 = relu([x[src]|ea] @ W_i + b_i), scatter M[dst] += h0.
// CTA = 128 threads, 64 edges; warp = 32 rows x 64 cols; K=80 (5 k16-tiles).
// (unchanged from the 389.6us best — one-variable discipline)
// ---------------------------------------------------------------------------
#define EA_HI   0
#define EA_LO   11264
#define E_SDST  22528
#define E_SBIAS 22784
#define E_SMEM  23296

__global__ __launch_bounds__(128, 4) void k_edge(
    const float* __restrict__ x,
    const int*   __restrict__ src,
    const int*   __restrict__ dst,
    const float* __restrict__ ea,
    const float* __restrict__ bi,
    int E)
{
    extern __shared__ char smem[];
    const uint32_t sb = smem_u32(smem);
    const int tid = threadIdx.x;
    const int e0 = blockIdx.x * 64;

    // ---- stage A: 2 threads per row, 40 k-floats each ----
    {
        const int row = tid >> 1, p = tid & 1;
        int e = e0 + row;
        int ec = (e < E) ? e : (E - 1);
        int s = src[ec];
        char* aH = smem + EA_HI;
        char* aL = smem + EA_LO;
        uint32_t off = (uint32_t)row * RSTRE + p * 80;   // (p*40 k) * 2B
        if (p == 0) {
            stage4<10>(aH, aL, off, (const float4*)(x + (size_t)s * 64));
        } else {
            stage4<6>(aH, aL, off,      (const float4*)(x + (size_t)s * 64 + 40));
            stage4<4>(aH, aL, off + 48, (const float4*)(ea + (size_t)ec * 16));
        }
        if (tid < 64) {
            int e2 = e0 + tid;
            ((int*)(smem + E_SDST))[tid] = dst[(e2 < E) ? e2 : (E - 1)];
        }
        ((float*)(smem + E_SBIAS))[tid] = bi[tid];
    }
    __syncthreads();

    // ---- mainloop ----
    const int l = tid & 31, w = tid >> 5;
    const int slab = (w >> 1) * 32, ch = w & 1;
    const uint32_t arow = (uint32_t)(slab + ((l >> 3) & 1) * 8 + (l & 7));
    const uint32_t a0 = sb + arow * RSTRE + ((l >> 4) << 4);
    const uint32_t a1 = a0 + 16 * RSTRE;

    float acc[64];
    #pragma unroll
    for (int i = 0; i < 64; i++) acc[i] = 0.f;

    const uint4* __restrict__ Bf = (const uint4*)g_Bfe;

    #pragma unroll
    for (int kt = 0; kt < 5; kt++) {
        uint32_t ah0[4], ah1[4], al0[4], al1[4];
        ldm4(ah0, a0 + EA_HI + kt * 32);
        ldm4(ah1, a1 + EA_HI + kt * 32);
        ldm4(al0, a0 + EA_LO + kt * 32);
        ldm4(al1, a1 + EA_LO + kt * 32);
        #pragma unroll
        for (int j = 0; j < 8; j++) {
            uint4 bf = Bf[(size_t)((kt * 16 + ch * 8 + j) * 32 + l)];
            float* c0 = acc + j * 8;
            float* c1 = acc + j * 8 + 4;
            mma16816(c0, ah0, bf.x, bf.y);  mma16816(c1, ah1, bf.x, bf.y);
            mma16816(c0, ah0, bf.z, bf.w);  mma16816(c1, ah1, bf.z, bf.w);
            mma16816(c0, al0, bf.x, bf.y);  mma16816(c1, al1, bf.x, bf.y);
        }
    }

    // ---- epilogue: bias + relu + pair-exchange -> red.v4 scatter (4 rows) ----
    {
        const int r0 = slab + (l >> 2);
        const int* sdst = (const int*)(smem + E_SDST);
        const int dr[4] = { sdst[r0], sdst[r0 + 8], sdst[r0 + 16], sdst[r0 + 24] };
        const bool dok[4] = { (e0 + r0) < E, (e0 + r0 + 8) < E,
                              (e0 + r0 + 16) < E, (e0 + r0 + 24) < E };
        const float* sbias = (const float*)(smem + E_SBIAS);
        #pragma unroll
        for (int j = 0; j < 8; j++) {
            int c0 = ch * 64 + j * 8 + (l & 3) * 2;
            float b0 = sbias[c0], b1 = sbias[c0 + 1];
            int cb = ch * 64 + j * 8 + ((l & 2) << 1);
            #pragma unroll
            for (int h = 0; h < 2; h++) {
                float v0 = fmaxf(acc[j * 8 + h * 4 + 0] + b0, 0.f);
                float v1 = fmaxf(acc[j * 8 + h * 4 + 1] + b1, 0.f);
                float v2 = fmaxf(acc[j * 8 + h * 4 + 2] + b0, 0.f);
                float v3 = fmaxf(acc[j * 8 + h * 4 + 3] + b1, 0.f);
                float u0 = __shfl_xor_sync(~0u, v0, 1);
                float u1 = __shfl_xor_sync(~0u, v1, 1);
                float u2 = __shfl_xor_sync(~0u, v2, 1);
                float u3 = __shfl_xor_sync(~0u, v3, 1);
                if (!(l & 1)) {
                    if (dok[h * 2])
                        red_add_v4(g_M + (size_t)dr[h * 2] * HID + cb, v0, v1, u0, u1);
                } else {
                    if (dok[h * 2 + 1])
                        red_add_v4(g_M + (size_t)dr[h * 2 + 1] * HID + cb, u2, u3, v2, v3);
                }
            }
        }
    }
}

// ---------------------------------------------------------------------------
// Kernel 2: nodes. out = relu([x|M] @ W_o + b_o).
// CTA = 128 threads, 64 nodes; warp = 32 rows x 64 cols; K=192 as TWO phases
// of 96 (panel 26.6KB -> smem no longer caps occupancy; regs capped for
// 5 CTAs/SM = 20 warps).
// ---------------------------------------------------------------------------
#define NA_HI   0
#define NA_LO   13312     // 64 * 208
#define N_SBIAS 26624
#define N_SMEM  27136

__global__ __launch_bounds__(128, 5) void k_node(
    const float* __restrict__ x,
    const float* __restrict__ bo,
    float*       __restrict__ out,
    int N)
{
    extern __shared__ char smem[];
    const uint32_t sb = smem_u32(smem);
    const int tid = threadIdx.x;
    const int n0 = blockIdx.x * 64;

    const int l = tid & 31, w = tid >> 5;
    const int slab = (w >> 1) * 32, ch = w & 1;
    const uint32_t arow = (uint32_t)(slab + ((l >> 3) & 1) * 8 + (l & 7));
    const uint32_t a0 = sb + arow * RSTRN + ((l >> 4) << 4);
    const uint32_t a1 = a0 + 16 * RSTRN;

    const int row = tid >> 1, p = tid & 1;
    int nn0 = n0 + row;
    int nc = (nn0 < N) ? nn0 : (N - 1);
    const float* xr = x + (size_t)nc * 64;
    const float* mr = g_M + (size_t)nc * HID;

    float acc[64];
    #pragma unroll
    for (int i = 0; i < 64; i++) acc[i] = 0.f;

    const uint4* __restrict__ Bf = (const uint4*)g_Bfn;

    #pragma unroll
    for (int ph = 0; ph < 2; ph++) {
        if (ph) __syncthreads();   // previous phase's compute done before restage
        // ---- stage A phase: 2 threads/row, 48 k-floats (12 float4) each ----
        {
            char* aH = smem + NA_HI;
            char* aL = smem + NA_LO;
            uint32_t off = (uint32_t)row * RSTRN + p * 96;   // (p*48 k) * 2B
            if (ph == 0) {
                // k 0..95 = x[0:64] | M[0:32]
                if (p == 0) {
                    stage4<12>(aH, aL, off, (const float4*)xr);
                } else {
                    stage4<4>(aH, aL, off,      (const float4*)(xr + 48));
                    stage4<8>(aH, aL, off + 32, (const float4*)mr);
                }
            } else {
                // k 96..191 = M[32:128]
                stage4<12>(aH, aL, off, (const float4*)(mr + 32 + p * 48));
            }
            if (ph == 0) ((float*)(smem + N_SBIAS))[tid] = bo[tid];
        }
        __syncthreads();

        // ---- mainloop: 6 k16-tiles this phase ----
        #pragma unroll
        for (int kt = 0; kt < 6; kt++) {
            uint32_t ah0[4], ah1[4], al0[4], al1[4];
            ldm4(ah0, a0 + NA_HI + kt * 32);
            ldm4(ah1, a1 + NA_HI + kt * 32);
            ldm4(al0, a0 + NA_LO + kt * 32);
            ldm4(al1, a1 + NA_LO + kt * 32);
            #pragma unroll
            for (int j = 0; j < 8; j++) {
                uint4 bf = Bf[(size_t)(((ph * 6 + kt) * 16 + ch * 8 + j) * 32 + l)];
                float* c0 = acc + j * 8;
                float* c1 = acc + j * 8 + 4;
                mma16816(c0, ah0, bf.x, bf.y);  mma16816(c1, ah1, bf.x, bf.y);
                mma16816(c0, ah0, bf.z, bf.w);  mma16816(c1, ah1, bf.z, bf.w);
                mma16816(c0, al0, bf.x, bf.y);  mma16816(c1, al1, bf.x, bf.y);
            }
        }
    }

    // ---- epilogue: bias + relu + pair-exchange -> float4 stores (4 rows) ----
    {
        const int r0 = slab + (l >> 2);
        const int nr[4] = { n0 + r0, n0 + r0 + 8, n0 + r0 + 16, n0 + r0 + 24 };
        const bool dok[4] = { nr[0] < N, nr[1] < N, nr[2] < N, nr[3] < N };
        const float* sbias = (const float*)(smem + N_SBIAS);
        #pragma unroll
        for (int j = 0; j < 8; j++) {
            int c0 = ch * 64 + j * 8 + (l & 3) * 2;
            float b0 = sbias[c0], b1 = sbias[c0 + 1];
            int cb = ch * 64 + j * 8 + ((l & 2) << 1);
            #pragma unroll
            for (int h = 0; h < 2; h++) {
                float v0 = fmaxf(acc[j * 8 + h * 4 + 0] + b0, 0.f);
                float v1 = fmaxf(acc[j * 8 + h * 4 + 1] + b1, 0.f);
                float v2 = fmaxf(acc[j * 8 + h * 4 + 2] + b0, 0.f);
                float v3 = fmaxf(acc[j * 8 + h * 4 + 3] + b1, 0.f);
                float u0 = __shfl_xor_sync(~0u, v0, 1);
                float u1 = __shfl_xor_sync(~0u, v1, 1);
                float u2 = __shfl_xor_sync(~0u, v2, 1);
                float u3 = __shfl_xor_sync(~0u, v3, 1);
                if (!(l & 1)) {
                    if (dok[h * 2])
                        *(float4*)(out + (size_t)nr[h * 2] * HID + cb) = make_float4(v0, v1, u0, u1);
                } else {
                    if (dok[h * 2 + 1])
                        *(float4*)(out + (size_t)nr[h * 2 + 1] * HID + cb) = make_float4(u2, u3, v2, v3);
                }
            }
        }
    }
}

// ---------------------------------------------------------------------------
extern "C" void kernel_launch(void* const* d_in, const int* in_sizes, int n_in,
                              void* d_out, int out_size)
{
    const float* x  = (const float*)d_in[0];
    const int*   ei = (const int*)  d_in[1];
    const float* ea = (const float*)d_in[2];
    const float* Wi = (const float*)d_in[4];
    const float* bi = (const float*)d_in[5];
    // W_h / b_h provably unused: in-loop message cancels exactly (reverse pairs).
    const float* Wo = (const float*)d_in[8];
    const float* bo = (const float*)d_in[9];
    float* out = (float*)d_out;

    const int N = in_sizes[0] / 64;
    const int E = in_sizes[2] / 16;
    const int* src = ei;
    const int* dst = ei + E;

    const int prep_threads = (5 + 12) * 16 * 32;
    k_prep<<<(prep_threads + 255) / 256, 256>>>(Wi, Wo);
    const int n4 = (N * HID) / 4;
    k_zero<<<(n4 + 255) / 256, 256>>>(n4);
    k_edge<<<(E + 63) / 64, 128, E_SMEM>>>(x, src, dst, ea, bi, E);
    k_node<<<(N + 63) / 64, 128, N_SMEM>>>(x, bo, out, N);
}

// round 16
// speedup vs baseline: 1.2863x; 1.2863x over previous
#include <cuda_runtime.h>
#include <cuda_fp16.h>
#include <cstdint>

#define HID 128
#define N_MAX 400000
__device__ float g_M[(size_t)N_MAX * HID];

// Weights (fp16 hi term only) pre-arranged in mma.m16n8k16 B-fragment order:
// record idx = (kt*16 + nt)*32 + lane, 8 bytes = {bh0, bh1}
// where b0 covers k = kt*16+(lane%4)*2 (+1), b1 covers k+8, n = nt*8 + lane/4.
__device__ __align__(16) unsigned char g_Bfe[5  * 16 * 32 * 8];  // edge W_i  (K=80)
__device__ __align__(16) unsigned char g_Bfn[12 * 16 * 32 * 8];  // node W_o  (K=192)

// ---------------------------------------------------------------------------
// helpers
// ---------------------------------------------------------------------------
__device__ __forceinline__ uint32_t smem_u32(const void* p) {
    uint32_t a;
    asm("{ .reg .u64 t; cvta.to.shared.u64 t, %1; cvt.u32.u64 %0, t; }" : "=r"(a) : "l"(p));
    return a;
}
__device__ __forceinline__ void ldm4(uint32_t* r, uint32_t addr) {
    asm volatile("ldmatrix.sync.aligned.m8n8.x4.shared.b16 {%0,%1,%2,%3}, [%4];"
                 : "=r"(r[0]), "=r"(r[1]), "=r"(r[2]), "=r"(r[3]) : "r"(addr));
}
__device__ __forceinline__ void mma16816(float* c, const uint32_t* a, uint32_t b0, uint32_t b1) {
    asm volatile("mma.sync.aligned.m16n8k16.row.col.f32.f16.f16.f32 "
                 "{%0,%1,%2,%3}, {%4,%5,%6,%7}, {%8,%9}, {%0,%1,%2,%3};"
                 : "+f"(c[0]), "+f"(c[1]), "+f"(c[2]), "+f"(c[3])
                 : "r"(a[0]), "r"(a[1]), "r"(a[2]), "r"(a[3]), "r"(b0), "r"(b1));
}
__device__ __forceinline__ void red_add_v4(float* p, float a, float b, float c, float d) {
    asm volatile("red.global.add.v4.f32 [%0], {%1,%2,%3,%4};"
                 :: "l"(p), "f"(a), "f"(b), "f"(c), "f"(d) : "memory");
}
// fp16 2-term split of a float pair -> packed hi/lo f16x2, memory order [va, vb]
__device__ __forceinline__ void split2h(float va, float vb, uint32_t& hi, uint32_t& lo) {
    __half2 h = __floats2half2_rn(va, vb);
    float2 hf = __half22float2(h);
    __half2 l = __floats2half2_rn(va - hf.x, vb - hf.y);
    hi = *(uint32_t*)&h;
    lo = *(uint32_t*)&l;
}
// stage n4 float4s (4 k each) as split f16 pairs at byte offset `off` (8B per float4)
template<int N4>
__device__ __forceinline__ void stage4(char* aH, char* aL, uint32_t off, const float4* g) {
    #pragma unroll
    for (int j = 0; j < N4; j++) {
        float4 v = g[j];
        uint32_t h, lo;
        split2h(v.x, v.y, h, lo);
        *(uint32_t*)(aH + off + j * 8) = h;  *(uint32_t*)(aL + off + j * 8) = lo;
        split2h(v.z, v.w, h, lo);
        *(uint32_t*)(aH + off + j * 8 + 4) = h;  *(uint32_t*)(aL + off + j * 8 + 4) = lo;
    }
}

#define RSTRE 176   // edge A row stride: 80 k * 2B + 16B pad (8-phase ldmatrix)
#define RSTRN 400   // node A row stride: 192 k * 2B + 16B pad

// ---------------------------------------------------------------------------
// Kernel P: write weights (fp16 hi only) in B-fragment order
// ---------------------------------------------------------------------------
__global__ void k_prep(const float* __restrict__ Wi, const float* __restrict__ Wo) {
    int t = blockIdx.x * blockDim.x + threadIdx.x;
    if (t < 5 * 16 * 32) {
        int l = t & 31, nt = (t >> 5) & 15, kt = t >> 9;
        int n = nt * 8 + (l >> 2), k0 = kt * 16 + (l & 3) * 2;
        __half2 b0 = __floats2half2_rn(Wi[k0 * 128 + n],       Wi[(k0 + 1) * 128 + n]);
        __half2 b1 = __floats2half2_rn(Wi[(k0 + 8) * 128 + n], Wi[(k0 + 9) * 128 + n]);
        ((uint2*)g_Bfe)[t] = make_uint2(*(uint32_t*)&b0, *(uint32_t*)&b1);
    }
    int t2 = t - 5 * 16 * 32;
    if (t2 >= 0 && t2 < 12 * 16 * 32) {
        int l = t2 & 31, nt = (t2 >> 5) & 15, kt = t2 >> 9;
        int n = nt * 8 + (l >> 2), k0 = kt * 16 + (l & 3) * 2;
        __half2 b0 = __floats2half2_rn(Wo[k0 * 128 + n],       Wo[(k0 + 1) * 128 + n]);
        __half2 b1 = __floats2half2_rn(Wo[(k0 + 8) * 128 + n], Wo[(k0 + 9) * 128 + n]);
        ((uint2*)g_Bfn)[t2] = make_uint2(*(uint32_t*)&b0, *(uint32_t*)&b1);
    }
}

// ---------------------------------------------------------------------------
// Kernel 0: zero the message buffer
// ---------------------------------------------------------------------------
__global__ void k_zero(int n4) {
    int i = blockIdx.x * blockDim.x + threadIdx.x;
    if (i < n4) ((float4*)g_M)[i] = make_float4(0.f, 0.f, 0.f, 0.f);
}

// ---------------------------------------------------------------------------
// Kernel 1: edges. h0 = relu([x[src]|ea] @ W_i + b_i), scatter M[dst] += h0.
// CTA = 128 threads, 64 edges; warp = 32 rows x 64 cols; K=80 (5 k16-tiles).
// fp16: A = Ah + Al (exact), B = hi only -> 4 MMAs per j instead of 6.
// ---------------------------------------------------------------------------
#define EA_HI   0
#define EA_LO   11264
#define E_SDST  22528
#define E_SBIAS 22784
#define E_SMEM  23296

__global__ __launch_bounds__(128, 4) void k_edge(
    const float* __restrict__ x,
    const int*   __restrict__ src,
    const int*   __restrict__ dst,
    const float* __restrict__ ea,
    const float* __restrict__ bi,
    int E)
{
    extern __shared__ char smem[];
    const uint32_t sb = smem_u32(smem);
    const int tid = threadIdx.x;
    const int e0 = blockIdx.x * 64;

    // ---- stage A: 2 threads per row, 40 k-floats each ----
    {
        const int row = tid >> 1, p = tid & 1;
        int e = e0 + row;
        int ec = (e < E) ? e : (E - 1);
        int s = src[ec];
        char* aH = smem + EA_HI;
        char* aL = smem + EA_LO;
        uint32_t off = (uint32_t)row * RSTRE + p * 80;   // (p*40 k) * 2B
        if (p == 0) {
            stage4<10>(aH, aL, off, (const float4*)(x + (size_t)s * 64));
        } else {
            stage4<6>(aH, aL, off,      (const float4*)(x + (size_t)s * 64 + 40));
            stage4<4>(aH, aL, off + 48, (const float4*)(ea + (size_t)ec * 16));
        }
        if (tid < 64) {
            int e2 = e0 + tid;
            ((int*)(smem + E_SDST))[tid] = dst[(e2 < E) ? e2 : (E - 1)];
        }
        ((float*)(smem + E_SBIAS))[tid] = bi[tid];
    }
    __syncthreads();

    // ---- mainloop ----
    const int l = tid & 31, w = tid >> 5;
    const int slab = (w >> 1) * 32, ch = w & 1;
    const uint32_t arow = (uint32_t)(slab + ((l >> 3) & 1) * 8 + (l & 7));
    const uint32_t a0 = sb + arow * RSTRE + ((l >> 4) << 4);
    const uint32_t a1 = a0 + 16 * RSTRE;

    float acc[64];
    #pragma unroll
    for (int i = 0; i < 64; i++) acc[i] = 0.f;

    const uint2* __restrict__ Bf = (const uint2*)g_Bfe;

    #pragma unroll
    for (int kt = 0; kt < 5; kt++) {
        uint32_t ah0[4], ah1[4], al0[4], al1[4];
        ldm4(ah0, a0 + EA_HI + kt * 32);
        ldm4(ah1, a1 + EA_HI + kt * 32);
        ldm4(al0, a0 + EA_LO + kt * 32);
        ldm4(al1, a1 + EA_LO + kt * 32);
        #pragma unroll
        for (int j = 0; j < 8; j++) {
            uint2 bf = Bf[(size_t)((kt * 16 + ch * 8 + j) * 32 + l)];
            float* c0 = acc + j * 8;
            float* c1 = acc + j * 8 + 4;
            mma16816(c0, ah0, bf.x, bf.y);  mma16816(c1, ah1, bf.x, bf.y);
            mma16816(c0, al0, bf.x, bf.y);  mma16816(c1, al1, bf.x, bf.y);
        }
    }

    // ---- epilogue: bias + relu + pair-exchange -> red.v4 scatter (4 rows) ----
    {
        const int r0 = slab + (l >> 2);
        const int* sdst = (const int*)(smem + E_SDST);
        const int dr[4] = { sdst[r0], sdst[r0 + 8], sdst[r0 + 16], sdst[r0 + 24] };
        const bool dok[4] = { (e0 + r0) < E, (e0 + r0 + 8) < E,
                              (e0 + r0 + 16) < E, (e0 + r0 + 24) < E };
        const float* sbias = (const float*)(smem + E_SBIAS);
        #pragma unroll
        for (int j = 0; j < 8; j++) {
            int c0 = ch * 64 + j * 8 + (l & 3) * 2;
            float b0 = sbias[c0], b1 = sbias[c0 + 1];
            int cb = ch * 64 + j * 8 + ((l & 2) << 1);
            #pragma unroll
            for (int h = 0; h < 2; h++) {
                float v0 = fmaxf(acc[j * 8 + h * 4 + 0] + b0, 0.f);
                float v1 = fmaxf(acc[j * 8 + h * 4 + 1] + b1, 0.f);
                float v2 = fmaxf(acc[j * 8 + h * 4 + 2] + b0, 0.f);
                float v3 = fmaxf(acc[j * 8 + h * 4 + 3] + b1, 0.f);
                float u0 = __shfl_xor_sync(~0u, v0, 1);
                float u1 = __shfl_xor_sync(~0u, v1, 1);
                float u2 = __shfl_xor_sync(~0u, v2, 1);
                float u3 = __shfl_xor_sync(~0u, v3, 1);
                if (!(l & 1)) {
                    if (dok[h * 2])
                        red_add_v4(g_M + (size_t)dr[h * 2] * HID + cb, v0, v1, u0, u1);
                } else {
                    if (dok[h * 2 + 1])
                        red_add_v4(g_M + (size_t)dr[h * 2 + 1] * HID + cb, u2, u3, v2, v3);
                }
            }
        }
    }
}

// ---------------------------------------------------------------------------
// Kernel 2: nodes. out = relu([x|M] @ W_o + b_o).
// CTA = 128 threads, 64 nodes; warp = 32 rows x 64 cols; K=192 (12 k16-tiles),
// single-phase staging (R13-proven schedule), fp16 2-term arithmetic.
// ---------------------------------------------------------------------------
#define NA_HI   0
#define NA_LO   25600
#define N_SBIAS 51200
#define N_SMEM  51712

__global__ __launch_bounds__(128, 4) void k_node(
    const float* __restrict__ x,
    const float* __restrict__ bo,
    float*       __restrict__ out,
    int N)
{
    extern __shared__ char smem[];
    const uint32_t sb = smem_u32(smem);
    const int tid = threadIdx.x;
    const int n0 = blockIdx.x * 64;

    // ---- stage A: 2 threads per row, 96 k-floats each (concat [x | M]) ----
    {
        const int row = tid >> 1, p = tid & 1;
        int n = n0 + row;
        int nc = (n < N) ? n : (N - 1);
        char* aH = smem + NA_HI;
        char* aL = smem + NA_LO;
        uint32_t off = (uint32_t)row * RSTRN + p * 192;   // (p*96 k) * 2B
        const float* xr = x + (size_t)nc * 64;
        const float* mr = g_M + (size_t)nc * HID;
        if (p == 0) {
            stage4<16>(aH, aL, off,       (const float4*)xr);
            stage4<8>(aH, aL, off + 128, (const float4*)mr);
        } else {
            stage4<24>(aH, aL, off, (const float4*)(mr + 32));
        }
        ((float*)(smem + N_SBIAS))[tid] = bo[tid];
    }
    __syncthreads();

    // ---- mainloop ----
    const int l = tid & 31, w = tid >> 5;
    const int slab = (w >> 1) * 32, ch = w & 1;
    const uint32_t arow = (uint32_t)(slab + ((l >> 3) & 1) * 8 + (l & 7));
    const uint32_t a0 = sb + arow * RSTRN + ((l >> 4) << 4);
    const uint32_t a1 = a0 + 16 * RSTRN;

    float acc[64];
    #pragma unroll
    for (int i = 0; i < 64; i++) acc[i] = 0.f;

    const uint2* __restrict__ Bf = (const uint2*)g_Bfn;

    #pragma unroll 2
    for (int kt = 0; kt < 12; kt++) {
        uint32_t ah0[4], ah1[4], al0[4], al1[4];
        ldm4(ah0, a0 + NA_HI + kt * 32);
        ldm4(ah1, a1 + NA_HI + kt * 32);
        ldm4(al0, a0 + NA_LO + kt * 32);
        ldm4(al1, a1 + NA_LO + kt * 32);
        #pragma unroll
        for (int j = 0; j < 8; j++) {
            uint2 bf = Bf[(size_t)((kt * 16 + ch * 8 + j) * 32 + l)];
            float* c0 = acc + j * 8;
            float* c1 = acc + j * 8 + 4;
            mma16816(c0, ah0, bf.x, bf.y);  mma16816(c1, ah1, bf.x, bf.y);
            mma16816(c0, al0, bf.x, bf.y);  mma16816(c1, al1, bf.x, bf.y);
        }
    }

    // ---- epilogue: bias + relu + pair-exchange -> float4 stores (4 rows) ----
    {
        const int r0 = slab + (l >> 2);
        const int nr[4] = { n0 + r0, n0 + r0 + 8, n0 + r0 + 16, n0 + r0 + 24 };
        const bool dok[4] = { nr[0] < N, nr[1] < N, nr[2] < N, nr[3] < N };
        const float* sbias = (const float*)(smem + N_SBIAS);
        #pragma unroll
        for (int j = 0; j < 8; j++) {
            int c0 = ch * 64 + j * 8 + (l & 3) * 2;
            float b0 = sbias[c0], b1 = sbias[c0 + 1];
            int cb = ch * 64 + j * 8 + ((l & 2) << 1);
            #pragma unroll
            for (int h = 0; h < 2; h++) {
                float v0 = fmaxf(acc[j * 8 + h * 4 + 0] + b0, 0.f);
                float v1 = fmaxf(acc[j * 8 + h * 4 + 1] + b1, 0.f);
                float v2 = fmaxf(acc[j * 8 + h * 4 + 2] + b0, 0.f);
                float v3 = fmaxf(acc[j * 8 + h * 4 + 3] + b1, 0.f);
                float u0 = __shfl_xor_sync(~0u, v0, 1);
                float u1 = __shfl_xor_sync(~0u, v1, 1);
                float u2 = __shfl_xor_sync(~0u, v2, 1);
                float u3 = __shfl_xor_sync(~0u, v3, 1);
                if (!(l & 1)) {
                    if (dok[h * 2])
                        *(float4*)(out + (size_t)nr[h * 2] * HID + cb) = make_float4(v0, v1, u0, u1);
                } else {
                    if (dok[h * 2 + 1])
                        *(float4*)(out + (size_t)nr[h * 2 + 1] * HID + cb) = make_float4(u2, u3, v2, v3);
                }
            }
        }
    }
}

// ---------------------------------------------------------------------------
extern "C" void kernel_launch(void* const* d_in, const int* in_sizes, int n_in,
                              void* d_out, int out_size)
{
    const float* x  = (const float*)d_in[0];
    const int*   ei = (const int*)  d_in[1];
    const float* ea = (const float*)d_in[2];
    const float* Wi = (const float*)d_in[4];
    const float* bi = (const float*)d_in[5];
    // W_h / b_h provably unused: in-loop message cancels exactly (reverse pairs).
    const float* Wo = (const float*)d_in[8];
    const float* bo = (const float*)d_in[9];
    float* out = (float*)d_out;

    const int N = in_sizes[0] / 64;
    const int E = in_sizes[2] / 16;
    const int* src = ei;
    const int* dst = ei + E;

    cudaFuncSetAttribute(k_node, cudaFuncAttributeMaxDynamicSharedMemorySize, N_SMEM);

    const int prep_threads = (5 + 12) * 16 * 32;
    k_prep<<<(prep_threads + 255) / 256, 256>>>(Wi, Wo);
    const int n4 = (N * HID) / 4;
    k_zero<<<(n4 + 255) / 256, 256>>>(n4);
    k_edge<<<(E + 63) / 64, 128, E_SMEM>>>(x, src, dst, ea, bi, E);
    k_node<<<(N + 63) / 64, 128, N_SMEM>>>(x, bo, out, N);
}

// round 17
// speedup vs baseline: 1.3335x; 1.0367x over previous
#include <cuda_runtime.h>
#include <cuda_fp16.h>
#include <cstdint>

#define HID 128
#define N_MAX 400000
__device__ float g_M[(size_t)N_MAX * HID];

// Weights (fp16) pre-arranged in mma.m16n8k16 B-fragment order:
// record idx = (kt*16 + nt)*32 + lane, 8 bytes = {b0, b1}
// where b0 covers k = kt*16+(lane%4)*2 (+1), b1 covers k+8, n = nt*8 + lane/4.
__device__ __align__(16) unsigned char g_Bfe[5  * 16 * 32 * 8];  // edge W_i  (K=80)
__device__ __align__(16) unsigned char g_Bfn[12 * 16 * 32 * 8];  // node W_o  (K=192)

// ---------------------------------------------------------------------------
// helpers
// ---------------------------------------------------------------------------
__device__ __forceinline__ uint32_t smem_u32(const void* p) {
    uint32_t a;
    asm("{ .reg .u64 t; cvta.to.shared.u64 t, %1; cvt.u32.u64 %0, t; }" : "=r"(a) : "l"(p));
    return a;
}
__device__ __forceinline__ void ldm4(uint32_t* r, uint32_t addr) {
    asm volatile("ldmatrix.sync.aligned.m8n8.x4.shared.b16 {%0,%1,%2,%3}, [%4];"
                 : "=r"(r[0]), "=r"(r[1]), "=r"(r[2]), "=r"(r[3]) : "r"(addr));
}
__device__ __forceinline__ void mma16816(float* c, const uint32_t* a, uint32_t b0, uint32_t b1) {
    asm volatile("mma.sync.aligned.m16n8k16.row.col.f32.f16.f16.f32 "
                 "{%0,%1,%2,%3}, {%4,%5,%6,%7}, {%8,%9}, {%0,%1,%2,%3};"
                 : "+f"(c[0]), "+f"(c[1]), "+f"(c[2]), "+f"(c[3])
                 : "r"(a[0]), "r"(a[1]), "r"(a[2]), "r"(a[3]), "r"(b0), "r"(b1));
}
__device__ __forceinline__ void red_add_v4(float* p, float a, float b, float c, float d) {
    asm volatile("red.global.add.v4.f32 [%0], {%1,%2,%3,%4};"
                 :: "l"(p), "f"(a), "f"(b), "f"(c), "f"(d) : "memory");
}
// stage n4 float4s (4 k each) as fp16 pairs at byte offset `off` (8B per float4)
template<int N4>
__device__ __forceinline__ void stage4(char* aH, uint32_t off, const float4* g) {
    #pragma unroll
    for (int j = 0; j < N4; j++) {
        float4 v = g[j];
        __half2 h0 = __floats2half2_rn(v.x, v.y);
        __half2 h1 = __floats2half2_rn(v.z, v.w);
        *(uint32_t*)(aH + off + j * 8)     = *(uint32_t*)&h0;
        *(uint32_t*)(aH + off + j * 8 + 4) = *(uint32_t*)&h1;
    }
}

#define RSTRE 176   // edge A row stride: 80 k * 2B + 16B pad (8-phase ldmatrix)
#define RSTRN 400   // node A row stride: 192 k * 2B + 16B pad

// ---------------------------------------------------------------------------
// Kernel P: write weights (fp16) in B-fragment order
// ---------------------------------------------------------------------------
__global__ void k_prep(const float* __restrict__ Wi, const float* __restrict__ Wo) {
    int t = blockIdx.x * blockDim.x + threadIdx.x;
    if (t < 5 * 16 * 32) {
        int l = t & 31, nt = (t >> 5) & 15, kt = t >> 9;
        int n = nt * 8 + (l >> 2), k0 = kt * 16 + (l & 3) * 2;
        __half2 b0 = __floats2half2_rn(Wi[k0 * 128 + n],       Wi[(k0 + 1) * 128 + n]);
        __half2 b1 = __floats2half2_rn(Wi[(k0 + 8) * 128 + n], Wi[(k0 + 9) * 128 + n]);
        ((uint2*)g_Bfe)[t] = make_uint2(*(uint32_t*)&b0, *(uint32_t*)&b1);
    }
    int t2 = t - 5 * 16 * 32;
    if (t2 >= 0 && t2 < 12 * 16 * 32) {
        int l = t2 & 31, nt = (t2 >> 5) & 15, kt = t2 >> 9;
        int n = nt * 8 + (l >> 2), k0 = kt * 16 + (l & 3) * 2;
        __half2 b0 = __floats2half2_rn(Wo[k0 * 128 + n],       Wo[(k0 + 1) * 128 + n]);
        __half2 b1 = __floats2half2_rn(Wo[(k0 + 8) * 128 + n], Wo[(k0 + 9) * 128 + n]);
        ((uint2*)g_Bfn)[t2] = make_uint2(*(uint32_t*)&b0, *(uint32_t*)&b1);
    }
}

// ---------------------------------------------------------------------------
// Kernel 0: zero the message buffer
// ---------------------------------------------------------------------------
__global__ void k_zero(int n4) {
    int i = blockIdx.x * blockDim.x + threadIdx.x;
    if (i < n4) ((float4*)g_M)[i] = make_float4(0.f, 0.f, 0.f, 0.f);
}

// ---------------------------------------------------------------------------
// Kernel 1: edges. h0 = relu([x[src]|ea] @ W_i + b_i), scatter M[dst] += h0.
// CTA = 128 threads, 64 edges; warp = 32 rows x 64 cols; K=80 (5 k16-tiles).
// Pure fp16 operands, fp32 accumulate: 2 MMAs per j.
// ---------------------------------------------------------------------------
#define EA      0
#define E_SDST  11264
#define E_SBIAS 11776
#define E_SMEM  12288

__global__ __launch_bounds__(128, 5) void k_edge(
    const float* __restrict__ x,
    const int*   __restrict__ src,
    const int*   __restrict__ dst,
    const float* __restrict__ ea,
    const float* __restrict__ bi,
    int E)
{
    extern __shared__ char smem[];
    const uint32_t sb = smem_u32(smem);
    const int tid = threadIdx.x;
    const int e0 = blockIdx.x * 64;

    // ---- stage A: 2 threads per row, 40 k-floats each ----
    {
        const int row = tid >> 1, p = tid & 1;
        int e = e0 + row;
        int ec = (e < E) ? e : (E - 1);
        int s = src[ec];
        char* aH = smem + EA;
        uint32_t off = (uint32_t)row * RSTRE + p * 80;   // (p*40 k) * 2B
        if (p == 0) {
            stage4<10>(aH, off, (const float4*)(x + (size_t)s * 64));
        } else {
            stage4<6>(aH, off,      (const float4*)(x + (size_t)s * 64 + 40));
            stage4<4>(aH, off + 48, (const float4*)(ea + (size_t)ec * 16));
        }
        if (tid < 64) {
            int e2 = e0 + tid;
            ((int*)(smem + E_SDST))[tid] = dst[(e2 < E) ? e2 : (E - 1)];
        }
        ((float*)(smem + E_SBIAS))[tid] = bi[tid];
    }
    __syncthreads();

    // ---- mainloop ----
    const int l = tid & 31, w = tid >> 5;
    const int slab = (w >> 1) * 32, ch = w & 1;
    const uint32_t arow = (uint32_t)(slab + ((l >> 3) & 1) * 8 + (l & 7));
    const uint32_t a0 = sb + EA + arow * RSTRE + ((l >> 4) << 4);
    const uint32_t a1 = a0 + 16 * RSTRE;

    float acc[64];
    #pragma unroll
    for (int i = 0; i < 64; i++) acc[i] = 0.f;

    const uint2* __restrict__ Bf = (const uint2*)g_Bfe;

    #pragma unroll
    for (int kt = 0; kt < 5; kt++) {
        uint32_t ah0[4], ah1[4];
        ldm4(ah0, a0 + kt * 32);
        ldm4(ah1, a1 + kt * 32);
        #pragma unroll
        for (int j = 0; j < 8; j++) {
            uint2 bf = Bf[(size_t)((kt * 16 + ch * 8 + j) * 32 + l)];
            mma16816(acc + j * 8,     ah0, bf.x, bf.y);
            mma16816(acc + j * 8 + 4, ah1, bf.x, bf.y);
        }
    }

    // ---- epilogue: bias + relu + pair-exchange -> red.v4 scatter (4 rows) ----
    {
        const int r0 = slab + (l >> 2);
        const int* sdst = (const int*)(smem + E_SDST);
        const int dr[4] = { sdst[r0], sdst[r0 + 8], sdst[r0 + 16], sdst[r0 + 24] };
        const bool dok[4] = { (e0 + r0) < E, (e0 + r0 + 8) < E,
                              (e0 + r0 + 16) < E, (e0 + r0 + 24) < E };
        const float* sbias = (const float*)(smem + E_SBIAS);
        #pragma unroll
        for (int j = 0; j < 8; j++) {
            int c0 = ch * 64 + j * 8 + (l & 3) * 2;
            float b0 = sbias[c0], b1 = sbias[c0 + 1];
            int cb = ch * 64 + j * 8 + ((l & 2) << 1);
            #pragma unroll
            for (int h = 0; h < 2; h++) {
                float v0 = fmaxf(acc[j * 8 + h * 4 + 0] + b0, 0.f);
                float v1 = fmaxf(acc[j * 8 + h * 4 + 1] + b1, 0.f);
                float v2 = fmaxf(acc[j * 8 + h * 4 + 2] + b0, 0.f);
                float v3 = fmaxf(acc[j * 8 + h * 4 + 3] + b1, 0.f);
                float u0 = __shfl_xor_sync(~0u, v0, 1);
                float u1 = __shfl_xor_sync(~0u, v1, 1);
                float u2 = __shfl_xor_sync(~0u, v2, 1);
                float u3 = __shfl_xor_sync(~0u, v3, 1);
                if (!(l & 1)) {
                    if (dok[h * 2])
                        red_add_v4(g_M + (size_t)dr[h * 2] * HID + cb, v0, v1, u0, u1);
                } else {
                    if (dok[h * 2 + 1])
                        red_add_v4(g_M + (size_t)dr[h * 2 + 1] * HID + cb, u2, u3, v2, v3);
                }
            }
        }
    }
}

// ---------------------------------------------------------------------------
// Kernel 2: nodes. out = relu([x|M] @ W_o + b_o).
// CTA = 128 threads, 64 nodes; warp = 32 rows x 64 cols; K=192 (12 k16-tiles).
// Pure fp16 operands, fp32 accumulate: 2 MMAs per j.
// ---------------------------------------------------------------------------
#define NA      0
#define N_SBIAS 25600
#define N_SMEM  26112

__global__ __launch_bounds__(128, 5) void k_node(
    const float* __restrict__ x,
    const float* __restrict__ bo,
    float*       __restrict__ out,
    int N)
{
    extern __shared__ char smem[];
    const uint32_t sb = smem_u32(smem);
    const int tid = threadIdx.x;
    const int n0 = blockIdx.x * 64;

    // ---- stage A: 2 threads per row, 96 k-floats each (concat [x | M]) ----
    {
        const int row = tid >> 1, p = tid & 1;
        int n = n0 + row;
        int nc = (n < N) ? n : (N - 1);
        char* aH = smem + NA;
        uint32_t off = (uint32_t)row * RSTRN + p * 192;   // (p*96 k) * 2B
        const float* xr = x + (size_t)nc * 64;
        const float* mr = g_M + (size_t)nc * HID;
        if (p == 0) {
            stage4<16>(aH, off,       (const float4*)xr);
            stage4<8>(aH, off + 128, (const float4*)mr);
        } else {
            stage4<24>(aH, off, (const float4*)(mr + 32));
        }
        ((float*)(smem + N_SBIAS))[tid] = bo[tid];
    }
    __syncthreads();

    // ---- mainloop ----
    const int l = tid & 31, w = tid >> 5;
    const int slab = (w >> 1) * 32, ch = w & 1;
    const uint32_t arow = (uint32_t)(slab + ((l >> 3) & 1) * 8 + (l & 7));
    const uint32_t a0 = sb + NA + arow * RSTRN + ((l >> 4) << 4);
    const uint32_t a1 = a0 + 16 * RSTRN;

    float acc[64];
    #pragma unroll
    for (int i = 0; i < 64; i++) acc[i] = 0.f;

    const uint2* __restrict__ Bf = (const uint2*)g_Bfn;

    #pragma unroll 3
    for (int kt = 0; kt < 12; kt++) {
        uint32_t ah0[4], ah1[4];
        ldm4(ah0, a0 + kt * 32);
        ldm4(ah1, a1 + kt * 32);
        #pragma unroll
        for (int j = 0; j < 8; j++) {
            uint2 bf = Bf[(size_t)((kt * 16 + ch * 8 + j) * 32 + l)];
            mma16816(acc + j * 8,     ah0, bf.x, bf.y);
            mma16816(acc + j * 8 + 4, ah1, bf.x, bf.y);
        }
    }

    // ---- epilogue: bias + relu + pair-exchange -> float4 stores (4 rows) ----
    {
        const int r0 = slab + (l >> 2);
        const int nr[4] = { n0 + r0, n0 + r0 + 8, n0 + r0 + 16, n0 + r0 + 24 };
        const bool dok[4] = { nr[0] < N, nr[1] < N, nr[2] < N, nr[3] < N };
        const float* sbias = (const float*)(smem + N_SBIAS);
        #pragma unroll
        for (int j = 0; j < 8; j++) {
            int c0 = ch * 64 + j * 8 + (l & 3) * 2;
            float b0 = sbias[c0], b1 = sbias[c0 + 1];
            int cb = ch * 64 + j * 8 + ((l & 2) << 1);
            #pragma unroll
            for (int h = 0; h < 2; h++) {
                float v0 = fmaxf(acc[j * 8 + h * 4 + 0] + b0, 0.f);
                float v1 = fmaxf(acc[j * 8 + h * 4 + 1] + b1, 0.f);
                float v2 = fmaxf(acc[j * 8 + h * 4 + 2] + b0, 0.f);
                float v3 = fmaxf(acc[j * 8 + h * 4 + 3] + b1, 0.f);
                float u0 = __shfl_xor_sync(~0u, v0, 1);
                float u1 = __shfl_xor_sync(~0u, v1, 1);
                float u2 = __shfl_xor_sync(~0u, v2, 1);
                float u3 = __shfl_xor_sync(~0u, v3, 1);
                if (!(l & 1)) {
                    if (dok[h * 2])
                        *(float4*)(out + (size_t)nr[h * 2] * HID + cb) = make_float4(v0, v1, u0, u1);
                } else {
                    if (dok[h * 2 + 1])
                        *(float4*)(out + (size_t)nr[h * 2 + 1] * HID + cb) = make_float4(u2, u3, v2, v3);
                }
            }
        }
    }
}

// ---------------------------------------------------------------------------
extern "C" void kernel_launch(void* const* d_in, const int* in_sizes, int n_in,
                              void* d_out, int out_size)
{
    const float* x  = (const float*)d_in[0];
    const int*   ei = (const int*)  d_in[1];
    const float* ea = (const float*)d_in[2];
    const float* Wi = (const float*)d_in[4];
    const float* bi = (const float*)d_in[5];
    // W_h / b_h provably unused: in-loop message cancels exactly (reverse pairs).
    const float* Wo = (const float*)d_in[8];
    const float* bo = (const float*)d_in[9];
    float* out = (float*)d_out;

    const int N = in_sizes[0] / 64;
    const int E = in_sizes[2] / 16;
    const int* src = ei;
    const int* dst = ei + E;

    const int prep_threads = (5 + 12) * 16 * 32;
    k_prep<<<(prep_threads + 255) / 256, 256>>>(Wi, Wo);
    const int n4 = (N * HID) / 4;
    k_zero<<<(n4 + 255) / 256, 256>>>(n4);
    k_edge<<<(E + 63) / 64, 128, E_SMEM>>>(x, src, dst, ea, bi, E);
    k_node<<<(N + 63) / 64, 128, N_SMEM>>>(x, bo, out, N);
}